// round 1
// baseline (speedup 1.0000x reference)
#include <cuda_runtime.h>
#include <float.h>

#define BT     (16 * 512)   // 8192 pairs
#define IDIM   80
#define HDIM   512
#define NSHIFT 159          // 2*IDIM - 1
#define PAD    79
#define KPLEN  238          // IDIM + 2*PAD

// Scratch for x_attn (allocation-free rule: __device__ global)
__device__ float g_xattn[BT * IDIM];

__device__ __forceinline__ float warpReduceSum(float v) {
#pragma unroll
    for (int o = 16; o; o >>= 1) v += __shfl_xor_sync(0xffffffffu, v, o);
    return v;
}

__device__ __forceinline__ float warpReduceMax(float v) {
#pragma unroll
    for (int o = 16; o; o >>= 1) v = fmaxf(v, __shfl_xor_sync(0xffffffffu, v, o));
    return v;
}

// ---------------------------------------------------------------------------
// Kernel 1: per (b,t) pair -> best-shift window, softmax gating, x_attn
// blockDim = 160 (5 warps), grid = BT
// ---------------------------------------------------------------------------
__global__ __launch_bounds__(160) void attn_kernel(
    const float* __restrict__ x, const float* __restrict__ y,
    float* __restrict__ xattn)
{
    const int p    = blockIdx.x;
    const int tid  = threadIdx.x;
    const int lane = tid & 31;
    const int warp = tid >> 5;

    __shared__ float kp[KPLEN + 2];   // zero-padded x (== key_pad)
    __shared__ float ys[IDIM];
    __shared__ float wred[5];
    __shared__ int   wredi[5];
    __shared__ float s_yn2, s_max, s_sum;
    __shared__ int   s_best;

    for (int i = tid; i < KPLEN + 2; i += 160) kp[i] = 0.0f;
    __syncthreads();

    float yv = 0.0f;
    if (tid < IDIM) {
        kp[PAD + tid] = x[(size_t)p * IDIM + tid];
        yv            = y[(size_t)p * IDIM + tid];
        ys[tid]       = yv;
    }
    __syncthreads();

    // ||y||^2
    {
        float v = warpReduceSum(yv * yv);
        if (lane == 0) wred[warp] = v;
        __syncthreads();
        if (tid == 0) {
            float t = 0.0f;
#pragma unroll
            for (int w = 0; w < 5; ++w) t += wred[w];
            s_yn2 = t;
        }
        __syncthreads();
    }
    const float yn2 = s_yn2;

    // Cosine similarity per shift; argmax with first-index tiebreak
    float sim  = -FLT_MAX;
    int   sidx = tid;
    if (tid < NSHIFT) {
        float dot = 0.0f, n2 = 0.0f;
#pragma unroll
        for (int i = 0; i < IDIM; ++i) {
            float k = kp[tid + i];
            dot = fmaf(k, ys[i], dot);
            n2  = fmaf(k, k,  n2);
        }
        float den = sqrtf(n2) * sqrtf(yn2);
        sim = (den > 0.0f) ? (dot / den) : 0.0f;
    }
#pragma unroll
    for (int o = 16; o; o >>= 1) {
        float ov = __shfl_xor_sync(0xffffffffu, sim,  o);
        int   oi = __shfl_xor_sync(0xffffffffu, sidx, o);
        if (ov > sim || (ov == sim && oi < sidx)) { sim = ov; sidx = oi; }
    }
    if (lane == 0) { wred[warp] = sim; wredi[warp] = sidx; }
    __syncthreads();
    if (tid == 0) {
        float bv = wred[0]; int bi = wredi[0];
#pragma unroll
        for (int w = 1; w < 5; ++w) {
            if (wred[w] > bv || (wred[w] == bv && wredi[w] < bi)) {
                bv = wred[w]; bi = wredi[w];
            }
        }
        s_best = bi;
    }
    __syncthreads();
    const int bs = s_best;

    // x_aug, score, softmax(score/10), x_attn
    float xa = 0.0f, sc = -FLT_MAX;
    if (tid < IDIM) {
        xa = kp[bs + tid];
        sc = xa * yv;
    }
    {
        float m = warpReduceMax(sc);
        if (lane == 0) wred[warp] = m;
        __syncthreads();
        if (tid == 0) {
            float t = -FLT_MAX;
#pragma unroll
            for (int w = 0; w < 5; ++w) t = fmaxf(t, wred[w]);
            s_max = t;
        }
        __syncthreads();
    }
    float e = (tid < IDIM) ? expf((sc - s_max) * 0.1f) : 0.0f;
    {
        float v = warpReduceSum(e);
        if (lane == 0) wred[warp] = v;
        __syncthreads();
        if (tid == 0) {
            float t = 0.0f;
#pragma unroll
            for (int w = 0; w < 5; ++w) t += wred[w];
            s_sum = t;
        }
        __syncthreads();
    }
    if (tid < IDIM) {
        float attn = e / s_sum;
        xattn[(size_t)p * IDIM + tid] = xa * attn;
    }
}

// ---------------------------------------------------------------------------
// Kernel 2: out[8192,512] = xattn[8192,80] @ W[512,80]^T + bias
// 128x128 tile, K=80 single stage, 256 threads, 8x8 microtile.
// Dynamic smem: As[80][128] + Bs[80][128] = 80 KB.
// ---------------------------------------------------------------------------
__global__ __launch_bounds__(256) void gemm_kernel(
    const float* __restrict__ A, const float* __restrict__ W,
    const float* __restrict__ bias, float* __restrict__ out)
{
    extern __shared__ float smem[];
    float* As = smem;                 // [80][128] k-major
    float* Bs = smem + IDIM * 128;    // [80][128] k-major

    const int bn  = blockIdx.x * 128; // over HDIM (512/128 = 4)
    const int bm  = blockIdx.y * 128; // over BT   (8192/128 = 64)
    const int tid = threadIdx.x;

    // Load & transpose tiles: 128 rows x 80 k; 2560 float4s / 256 threads = 10 each
#pragma unroll
    for (int t = 0; t < 10; ++t) {
        int idx = tid + t * 256;
        int row = idx / 20;
        int k4  = (idx % 20) * 4;
        float4 a = *reinterpret_cast<const float4*>(A + (size_t)(bm + row) * IDIM + k4);
        As[(k4 + 0) * 128 + row] = a.x;
        As[(k4 + 1) * 128 + row] = a.y;
        As[(k4 + 2) * 128 + row] = a.z;
        As[(k4 + 3) * 128 + row] = a.w;
        float4 b = *reinterpret_cast<const float4*>(W + (size_t)(bn + row) * IDIM + k4);
        Bs[(k4 + 0) * 128 + row] = b.x;
        Bs[(k4 + 1) * 128 + row] = b.y;
        Bs[(k4 + 2) * 128 + row] = b.z;
        Bs[(k4 + 3) * 128 + row] = b.w;
    }
    __syncthreads();

    const int tx = tid & 15;   // n micro-tile
    const int ty = tid >> 4;   // m micro-tile

    float acc[8][8];
#pragma unroll
    for (int i = 0; i < 8; ++i)
#pragma unroll
        for (int j = 0; j < 8; ++j) acc[i][j] = 0.0f;

#pragma unroll 4
    for (int k = 0; k < IDIM; ++k) {
        float4 a0 = *reinterpret_cast<const float4*>(&As[k * 128 + ty * 8]);
        float4 a1 = *reinterpret_cast<const float4*>(&As[k * 128 + ty * 8 + 4]);
        float4 b0 = *reinterpret_cast<const float4*>(&Bs[k * 128 + tx * 8]);
        float4 b1 = *reinterpret_cast<const float4*>(&Bs[k * 128 + tx * 8 + 4]);
        float av[8] = {a0.x, a0.y, a0.z, a0.w, a1.x, a1.y, a1.z, a1.w};
        float bv[8] = {b0.x, b0.y, b0.z, b0.w, b1.x, b1.y, b1.z, b1.w};
#pragma unroll
        for (int i = 0; i < 8; ++i)
#pragma unroll
            for (int j = 0; j < 8; ++j)
                acc[i][j] = fmaf(av[i], bv[j], acc[i][j]);
    }

#pragma unroll
    for (int i = 0; i < 8; ++i) {
        int m = bm + ty * 8 + i;
#pragma unroll
        for (int j = 0; j < 8; j += 4) {
            int n = bn + tx * 8 + j;
            float4 bb = *reinterpret_cast<const float4*>(bias + n);
            float4 o;
            o.x = acc[i][j + 0] + bb.x;
            o.y = acc[i][j + 1] + bb.y;
            o.z = acc[i][j + 2] + bb.z;
            o.w = acc[i][j + 3] + bb.w;
            *reinterpret_cast<float4*>(out + (size_t)m * HDIM + n) = o;
        }
    }
}

extern "C" void kernel_launch(void* const* d_in, const int* in_sizes, int n_in,
                              void* d_out, int out_size)
{
    const float* x    = (const float*)d_in[0];
    const float* y    = (const float*)d_in[1];
    const float* fc1w = (const float*)d_in[2];
    const float* fc1b = (const float*)d_in[3];
    float* out = (float*)d_out;

    float* xattn = nullptr;
    cudaGetSymbolAddress((void**)&xattn, g_xattn);

    attn_kernel<<<BT, 160>>>(x, y, xattn);

    const int smem_bytes = 2 * IDIM * 128 * (int)sizeof(float); // 81920
    cudaFuncSetAttribute(gemm_kernel, cudaFuncAttributeMaxDynamicSharedMemorySize, smem_bytes);
    gemm_kernel<<<dim3(HDIM / 128, BT / 128), 256, smem_bytes>>>(xattn, fc1w, fc1b, out);
}

// round 3
// speedup vs baseline: 1.8246x; 1.8246x over previous
#include <cuda_runtime.h>
#include <float.h>

#define BT     (16 * 512)   // 8192 pairs
#define IDIM   80
#define HDIM   512
#define NSHIFT 159          // 2*IDIM - 1
#define PAD    79
#define SKP    248          // padded keypad stride (238 + lane-tail overread)

// Scratch for x_attn (allocation-free rule: __device__ global)
__device__ float g_xattn[BT * IDIM];

__device__ __forceinline__ float warpReduceSum(float v) {
#pragma unroll
    for (int o = 16; o; o >>= 1) v += __shfl_xor_sync(0xffffffffu, v, o);
    return v;
}
__device__ __forceinline__ float warpReduceMax(float v) {
#pragma unroll
    for (int o = 16; o; o >>= 1) v = fmaxf(v, __shfl_xor_sync(0xffffffffu, v, o));
    return v;
}

// ---------------------------------------------------------------------------
// Kernel 1: warp-per-pair. Each lane owns 5 consecutive shifts with a sliding
// register window over kp. Dot AND window-norm are accumulated with direct
// fmaf in ascending-i order => bit-identical to the R1-validated numerics
// (argmax ordering depends only on dot_s / sqrt(n2_s)).
// ---------------------------------------------------------------------------
#define PAIRS_PER_BLK 8
__global__ __launch_bounds__(256) void attn_kernel(
    const float* __restrict__ x, const float* __restrict__ y,
    float* __restrict__ xattn)
{
    const int warp = threadIdx.x >> 5;
    const int lane = threadIdx.x & 31;
    const int p    = blockIdx.x * PAIRS_PER_BLK + warp;

    __shared__ float kp[PAIRS_PER_BLK][SKP];
    __shared__ float ys[PAIRS_PER_BLK][IDIM];
    float* kpw = kp[warp];
    float* ysw = ys[warp];

    for (int i = lane; i < SKP; i += 32) kpw[i] = 0.0f;
    __syncwarp();

    const float* xp = x + (size_t)p * IDIM;
    const float* yp = y + (size_t)p * IDIM;
    float yn2 = 0.0f;
    for (int i = lane; i < IDIM; i += 32) {
        kpw[PAD + i] = xp[i];
        float v = yp[i];
        ysw[i] = v;
        yn2 = fmaf(v, v, yn2);
    }
    yn2 = warpReduceSum(yn2);
    __syncwarp();

    const int base = lane * 5;
    float w0 = kpw[base + 0], w1 = kpw[base + 1], w2 = kpw[base + 2],
          w3 = kpw[base + 3], w4 = kpw[base + 4];

    float d0 = 0, d1 = 0, d2 = 0, d3 = 0, d4 = 0;
    float q0 = 0, q1 = 0, q2 = 0, q3 = 0, q4 = 0;
#pragma unroll
    for (int i = 0; i < IDIM; ++i) {
        float yv = ysw[i];
        d0 = fmaf(w0, yv, d0);  q0 = fmaf(w0, w0, q0);
        d1 = fmaf(w1, yv, d1);  q1 = fmaf(w1, w1, q1);
        d2 = fmaf(w2, yv, d2);  q2 = fmaf(w2, w2, q2);
        d3 = fmaf(w3, yv, d3);  q3 = fmaf(w3, w3, q3);
        d4 = fmaf(w4, yv, d4);  q4 = fmaf(w4, w4, q4);
        w0 = w1; w1 = w2; w2 = w3; w3 = w4;
        w4 = kpw[base + 5 + i];
    }

    const float yn = sqrtf(yn2);
    float dotv[5] = {d0, d1, d2, d3, d4};
    float n2v[5]  = {q0, q1, q2, q3, q4};
    float best = -FLT_MAX;
    int   bidx = 0;
#pragma unroll
    for (int j = 0; j < 5; ++j) {
        int s = base + j;
        if (s < NSHIFT) {
            float den = sqrtf(n2v[j]) * yn;
            float sim = (den > 0.0f) ? (dotv[j] / den) : 0.0f;
            if (sim > best) { best = sim; bidx = s; }   // ascending j => first idx
        }
    }
#pragma unroll
    for (int o = 16; o; o >>= 1) {
        float ov = __shfl_xor_sync(0xffffffffu, best, o);
        int   oi = __shfl_xor_sync(0xffffffffu, bidx, o);
        if (ov > best || (ov == best && oi < bidx)) { best = ov; bidx = oi; }
    }
    const int bs = bidx;   // uniform across warp after xor-reduce

    // x_aug, softmax(score/10), x_attn  (3 elems per lane: i, i+32, i+64)
    float xa[3], sc[3];
    float m = -FLT_MAX;
#pragma unroll
    for (int t = 0; t < 3; ++t) {
        int i = lane + t * 32;
        if (i < IDIM) {
            xa[t] = kpw[bs + i];
            sc[t] = xa[t] * ysw[i];
            m = fmaxf(m, sc[t]);
        }
    }
    m = warpReduceMax(m);
    float sum = 0.0f, e[3];
#pragma unroll
    for (int t = 0; t < 3; ++t) {
        int i = lane + t * 32;
        if (i < IDIM) { e[t] = expf((sc[t] - m) * 0.1f); sum += e[t]; }
    }
    sum = warpReduceSum(sum);
    const float inv = 1.0f / sum;
#pragma unroll
    for (int t = 0; t < 3; ++t) {
        int i = lane + t * 32;
        if (i < IDIM) xattn[(size_t)p * IDIM + i] = xa[t] * (e[t] * inv);
    }
}

// ---------------------------------------------------------------------------
// Kernel 2: out[8192,512] = xattn[8192,80] @ W[512,80]^T + bias
// Tensor cores: mma.sync.m16n8k8.tf32 with 2-term (hi/lo) split precision.
// Block 128x128, 8 warps (2x4), warp tile 64x32 (4x4 mma tiles).
// ---------------------------------------------------------------------------
#define SSTR 84   // smem k-stride (pad 80 -> 84: (20g+t)%32 conflict-free frags)

__device__ __forceinline__ unsigned f2tf(float f) {
    unsigned r;
    asm("cvt.rna.tf32.f32 %0, %1;" : "=r"(r) : "f"(f));
    return r;
}

__device__ __forceinline__ void mma_tf32(float d[4], const unsigned a[4],
                                         const unsigned b[2]) {
    asm("mma.sync.aligned.m16n8k8.row.col.f32.tf32.tf32.f32 "
        "{%0,%1,%2,%3}, {%4,%5,%6,%7}, {%8,%9}, {%0,%1,%2,%3};"
        : "+f"(d[0]), "+f"(d[1]), "+f"(d[2]), "+f"(d[3])
        : "r"(a[0]), "r"(a[1]), "r"(a[2]), "r"(a[3]), "r"(b[0]), "r"(b[1]));
}

__global__ __launch_bounds__(256) void gemm_kernel(
    const float* __restrict__ A, const float* __restrict__ W,
    const float* __restrict__ bias, float* __restrict__ out)
{
    extern __shared__ float smem[];
    float* As = smem;               // [128][SSTR] row-major (m, k)
    float* Bs = smem + 128 * SSTR;  // [128][SSTR] row-major (n, k)

    const int bn  = blockIdx.x * 128;
    const int bm  = blockIdx.y * 128;
    const int tid = threadIdx.x;
    const int warp = tid >> 5, lane = tid & 31;
    const int wm = warp >> 2;       // 0..1  (64 rows each)
    const int wn = warp & 3;        // 0..3  (32 cols each)
    const int g  = lane >> 2;       // groupID
    const int t  = lane & 3;        // threadID in group

    // Load tiles: 128 rows x 20 float4 each for A and B
#pragma unroll
    for (int it = 0; it < 10; ++it) {
        int idx = tid + it * 256;
        int row = idx / 20;
        int k4  = (idx % 20) * 4;
        float4 a = *reinterpret_cast<const float4*>(A + (size_t)(bm + row) * IDIM + k4);
        *reinterpret_cast<float4*>(&As[row * SSTR + k4]) = a;
        float4 b = *reinterpret_cast<const float4*>(W + (size_t)(bn + row) * IDIM + k4);
        *reinterpret_cast<float4*>(&Bs[row * SSTR + k4]) = b;
    }
    __syncthreads();

    float d[4][4][4];
#pragma unroll
    for (int mt = 0; mt < 4; ++mt)
#pragma unroll
        for (int nt = 0; nt < 4; ++nt)
#pragma unroll
            for (int r = 0; r < 4; ++r) d[mt][nt][r] = 0.0f;

#pragma unroll
    for (int k0 = 0; k0 < IDIM; k0 += 8) {
        unsigned ah[4][4], al[4][4];
#pragma unroll
        for (int mt = 0; mt < 4; ++mt) {
            int r0 = wm * 64 + mt * 16 + g;
            int r1 = r0 + 8;
            float v0 = As[r0 * SSTR + k0 + t];
            float v1 = As[r1 * SSTR + k0 + t];
            float v2 = As[r0 * SSTR + k0 + t + 4];
            float v3 = As[r1 * SSTR + k0 + t + 4];
            ah[mt][0] = f2tf(v0); al[mt][0] = f2tf(v0 - __uint_as_float(ah[mt][0]));
            ah[mt][1] = f2tf(v1); al[mt][1] = f2tf(v1 - __uint_as_float(ah[mt][1]));
            ah[mt][2] = f2tf(v2); al[mt][2] = f2tf(v2 - __uint_as_float(ah[mt][2]));
            ah[mt][3] = f2tf(v3); al[mt][3] = f2tf(v3 - __uint_as_float(ah[mt][3]));
        }
        unsigned bh[4][2], bl[4][2];
#pragma unroll
        for (int nt = 0; nt < 4; ++nt) {
            int nr = wn * 32 + nt * 8 + g;
            float v0 = Bs[nr * SSTR + k0 + t];
            float v1 = Bs[nr * SSTR + k0 + t + 4];
            bh[nt][0] = f2tf(v0); bl[nt][0] = f2tf(v0 - __uint_as_float(bh[nt][0]));
            bh[nt][1] = f2tf(v1); bl[nt][1] = f2tf(v1 - __uint_as_float(bh[nt][1]));
        }
#pragma unroll
        for (int mt = 0; mt < 4; ++mt)
#pragma unroll
            for (int nt = 0; nt < 4; ++nt) {
                mma_tf32(d[mt][nt], ah[mt], bh[nt]);   // hi*hi
                mma_tf32(d[mt][nt], ah[mt], bl[nt]);   // hi*lo
                mma_tf32(d[mt][nt], al[mt], bh[nt]);   // lo*hi
            }
    }

    // Epilogue: c0,c1 -> (row, 2t..2t+1); c2,c3 -> (row+8, 2t..2t+1)
#pragma unroll
    for (int mt = 0; mt < 4; ++mt) {
#pragma unroll
        for (int nt = 0; nt < 4; ++nt) {
            int row = bm + wm * 64 + mt * 16 + g;
            int col = bn + wn * 32 + nt * 8 + 2 * t;
            float b0 = __ldg(bias + col), b1 = __ldg(bias + col + 1);
            float2 o0 = make_float2(d[mt][nt][0] + b0, d[mt][nt][1] + b1);
            float2 o1 = make_float2(d[mt][nt][2] + b0, d[mt][nt][3] + b1);
            *reinterpret_cast<float2*>(out + (size_t)row * HDIM + col) = o0;
            *reinterpret_cast<float2*>(out + (size_t)(row + 8) * HDIM + col) = o1;
        }
    }
}

extern "C" void kernel_launch(void* const* d_in, const int* in_sizes, int n_in,
                              void* d_out, int out_size)
{
    const float* x    = (const float*)d_in[0];
    const float* y    = (const float*)d_in[1];
    const float* fc1w = (const float*)d_in[2];
    const float* fc1b = (const float*)d_in[3];
    float* out = (float*)d_out;

    float* xattn = nullptr;
    cudaGetSymbolAddress((void**)&xattn, g_xattn);

    attn_kernel<<<BT / PAIRS_PER_BLK, 256>>>(x, y, xattn);

    const int smem_bytes = 2 * 128 * SSTR * (int)sizeof(float);  // 86016
    cudaFuncSetAttribute(gemm_kernel,
                         cudaFuncAttributeMaxDynamicSharedMemorySize, smem_bytes);
    gemm_kernel<<<dim3(HDIM / 128, BT / 128), 256, smem_bytes>>>(xattn, fc1w, fc1b, out);
}

// round 4
// speedup vs baseline: 2.1895x; 1.2000x over previous
#include <cuda_runtime.h>
#include <float.h>

#define BT     (16 * 512)   // 8192 pairs
#define IDIM   80
#define HDIM   512
#define NSHIFT 159          // 2*IDIM - 1
#define PAD    79
#define SKP    248          // padded keypad stride (238 + lane-tail overread)

// Scratch for x_attn (allocation-free rule: __device__ global)
__device__ float g_xattn[BT * IDIM];

__device__ __forceinline__ float warpReduceSum(float v) {
#pragma unroll
    for (int o = 16; o; o >>= 1) v += __shfl_xor_sync(0xffffffffu, v, o);
    return v;
}
__device__ __forceinline__ float warpReduceMax(float v) {
#pragma unroll
    for (int o = 16; o; o >>= 1) v = fmaxf(v, __shfl_xor_sync(0xffffffffu, v, o));
    return v;
}

// ---------------------------------------------------------------------------
// Kernel 1 (UNCHANGED from R3 — numerics validated): warp-per-pair sliding
// register window; dot and window-norm via direct ascending fmaf.
// ---------------------------------------------------------------------------
#define PAIRS_PER_BLK 8
__global__ __launch_bounds__(256) void attn_kernel(
    const float* __restrict__ x, const float* __restrict__ y,
    float* __restrict__ xattn)
{
    const int warp = threadIdx.x >> 5;
    const int lane = threadIdx.x & 31;
    const int p    = blockIdx.x * PAIRS_PER_BLK + warp;

    __shared__ float kp[PAIRS_PER_BLK][SKP];
    __shared__ float ys[PAIRS_PER_BLK][IDIM];
    float* kpw = kp[warp];
    float* ysw = ys[warp];

    for (int i = lane; i < SKP; i += 32) kpw[i] = 0.0f;
    __syncwarp();

    const float* xp = x + (size_t)p * IDIM;
    const float* yp = y + (size_t)p * IDIM;
    float yn2 = 0.0f;
    for (int i = lane; i < IDIM; i += 32) {
        kpw[PAD + i] = xp[i];
        float v = yp[i];
        ysw[i] = v;
        yn2 = fmaf(v, v, yn2);
    }
    yn2 = warpReduceSum(yn2);
    __syncwarp();

    const int base = lane * 5;
    float w0 = kpw[base + 0], w1 = kpw[base + 1], w2 = kpw[base + 2],
          w3 = kpw[base + 3], w4 = kpw[base + 4];

    float d0 = 0, d1 = 0, d2 = 0, d3 = 0, d4 = 0;
    float q0 = 0, q1 = 0, q2 = 0, q3 = 0, q4 = 0;
#pragma unroll
    for (int i = 0; i < IDIM; ++i) {
        float yv = ysw[i];
        d0 = fmaf(w0, yv, d0);  q0 = fmaf(w0, w0, q0);
        d1 = fmaf(w1, yv, d1);  q1 = fmaf(w1, w1, q1);
        d2 = fmaf(w2, yv, d2);  q2 = fmaf(w2, w2, q2);
        d3 = fmaf(w3, yv, d3);  q3 = fmaf(w3, w3, q3);
        d4 = fmaf(w4, yv, d4);  q4 = fmaf(w4, w4, q4);
        w0 = w1; w1 = w2; w2 = w3; w3 = w4;
        w4 = kpw[base + 5 + i];
    }

    const float yn = sqrtf(yn2);
    float dotv[5] = {d0, d1, d2, d3, d4};
    float n2v[5]  = {q0, q1, q2, q3, q4};
    float best = -FLT_MAX;
    int   bidx = 0;
#pragma unroll
    for (int j = 0; j < 5; ++j) {
        int s = base + j;
        if (s < NSHIFT) {
            float den = sqrtf(n2v[j]) * yn;
            float sim = (den > 0.0f) ? (dotv[j] / den) : 0.0f;
            if (sim > best) { best = sim; bidx = s; }
        }
    }
#pragma unroll
    for (int o = 16; o; o >>= 1) {
        float ov = __shfl_xor_sync(0xffffffffu, best, o);
        int   oi = __shfl_xor_sync(0xffffffffu, bidx, o);
        if (ov > best || (ov == best && oi < bidx)) { best = ov; bidx = oi; }
    }
    const int bs = bidx;

    float xa[3], sc[3];
    float m = -FLT_MAX;
#pragma unroll
    for (int t = 0; t < 3; ++t) {
        int i = lane + t * 32;
        if (i < IDIM) {
            xa[t] = kpw[bs + i];
            sc[t] = xa[t] * ysw[i];
            m = fmaxf(m, sc[t]);
        }
    }
    m = warpReduceMax(m);
    float sum = 0.0f, e[3];
#pragma unroll
    for (int t = 0; t < 3; ++t) {
        int i = lane + t * 32;
        if (i < IDIM) { e[t] = expf((sc[t] - m) * 0.1f); sum += e[t]; }
    }
    sum = warpReduceSum(sum);
    const float inv = 1.0f / sum;
#pragma unroll
    for (int t = 0; t < 3; ++t) {
        int i = lane + t * 32;
        if (i < IDIM) xattn[(size_t)p * IDIM + i] = xa[t] * (e[t] * inv);
    }
}

// ---------------------------------------------------------------------------
// Kernel 2: out[8192,512] = xattn[8192,80] @ W[512,80]^T + bias
// bf16 2-term split (hi*hi + hi*lo + lo*hi) on mma.m16n8k16.bf16.
// smem holds interleaved (hi_pair, lo_pair) bf16x2 per k-pair, split ONCE at
// tile fill. Block 128x128, warp tile 64x32, frag loads are LDS.64.
// ---------------------------------------------------------------------------
#define SP 42   // uint2 (8B) stride per row: word-stride 84 => 20g mod 32 pattern

// Split two floats into packed bf16x2 hi and bf16x2 lo (low half = first elem)
__device__ __forceinline__ void split2(float v0, float v1,
                                       unsigned& hp, unsigned& lp) {
    asm("cvt.rn.bf16x2.f32 %0, %1, %2;" : "=r"(hp) : "f"(v1), "f"(v0));
    float h0 = __uint_as_float(hp << 16);
    float h1 = __uint_as_float(hp & 0xFFFF0000u);
    asm("cvt.rn.bf16x2.f32 %0, %1, %2;" : "=r"(lp) : "f"(v1 - h1), "f"(v0 - h0));
}

__device__ __forceinline__ void mma_bf16(float d[4],
                                         unsigned a0, unsigned a1,
                                         unsigned a2, unsigned a3,
                                         unsigned b0, unsigned b1) {
    asm("mma.sync.aligned.m16n8k16.row.col.f32.bf16.bf16.f32 "
        "{%0,%1,%2,%3}, {%4,%5,%6,%7}, {%8,%9}, {%0,%1,%2,%3};"
        : "+f"(d[0]), "+f"(d[1]), "+f"(d[2]), "+f"(d[3])
        : "r"(a0), "r"(a1), "r"(a2), "r"(a3), "r"(b0), "r"(b1));
}

__global__ __launch_bounds__(256, 2) void gemm_kernel(
    const float* __restrict__ A, const float* __restrict__ W,
    const float* __restrict__ bias, float* __restrict__ out)
{
    extern __shared__ unsigned smem_u[];
    uint2* Ax = reinterpret_cast<uint2*>(smem_u);            // [128][SP] (hi,lo)
    uint2* Bx = reinterpret_cast<uint2*>(smem_u) + 128 * SP; // [128][SP]

    const int bn  = blockIdx.x * 128;
    const int bm  = blockIdx.y * 128;
    const int tid = threadIdx.x;
    const int warp = tid >> 5, lane = tid & 31;
    const int wm = warp >> 2;       // 0..1
    const int wn = warp & 3;        // 0..3
    const int g  = lane >> 2;
    const int t  = lane & 3;

    // Fill: 128 rows x 20 float4 each; split to bf16 hi/lo pairs, STS.128
#pragma unroll
    for (int it = 0; it < 10; ++it) {
        int idx = tid + it * 256;
        int row = idx / 20;
        int k4  = (idx % 20) * 4;   // element offset; kpair c = k4/2 (even)
        int c   = k4 >> 1;

        float4 a = *reinterpret_cast<const float4*>(A + (size_t)(bm + row) * IDIM + k4);
        uint4 pa;
        split2(a.x, a.y, pa.x, pa.y);
        split2(a.z, a.w, pa.z, pa.w);
        *reinterpret_cast<uint4*>(&Ax[row * SP + c]) = pa;

        float4 b = *reinterpret_cast<const float4*>(W + (size_t)(bn + row) * IDIM + k4);
        uint4 pb;
        split2(b.x, b.y, pb.x, pb.y);
        split2(b.z, b.w, pb.z, pb.w);
        *reinterpret_cast<uint4*>(&Bx[row * SP + c]) = pb;
    }
    __syncthreads();

    float d[4][4][4];
#pragma unroll
    for (int mt = 0; mt < 4; ++mt)
#pragma unroll
        for (int nt = 0; nt < 4; ++nt)
#pragma unroll
            for (int r = 0; r < 4; ++r) d[mt][nt][r] = 0.0f;

    // K = 80 -> 5 chunks of k16 (8 kpairs each)
#pragma unroll
    for (int kc = 0; kc < 5; ++kc) {
        const int kb = kc * 8 + t;

        uint2 b0[4], b1[4];
#pragma unroll
        for (int nt = 0; nt < 4; ++nt) {
            int nr = (wn * 32 + nt * 8 + g) * SP + kb;
            b0[nt] = Bx[nr];
            b1[nt] = Bx[nr + 4];
        }

#pragma unroll
        for (int mt = 0; mt < 4; ++mt) {
            int r0 = (wm * 64 + mt * 16 + g) * SP + kb;
            uint2 a0 = Ax[r0];
            uint2 a1 = Ax[r0 + 8 * SP];
            uint2 a2 = Ax[r0 + 4];
            uint2 a3 = Ax[r0 + 8 * SP + 4];
#pragma unroll
            for (int nt = 0; nt < 4; ++nt) {
                mma_bf16(d[mt][nt], a0.x, a1.x, a2.x, a3.x, b0[nt].x, b1[nt].x); // hi*hi
                mma_bf16(d[mt][nt], a0.x, a1.x, a2.x, a3.x, b0[nt].y, b1[nt].y); // hi*lo
                mma_bf16(d[mt][nt], a0.y, a1.y, a2.y, a3.y, b0[nt].x, b1[nt].x); // lo*hi
            }
        }
    }

    // Epilogue: c0,c1 -> (row, 2t..2t+1); c2,c3 -> (row+8, 2t..2t+1)
#pragma unroll
    for (int mt = 0; mt < 4; ++mt) {
#pragma unroll
        for (int nt = 0; nt < 4; ++nt) {
            int row = bm + wm * 64 + mt * 16 + g;
            int col = bn + wn * 32 + nt * 8 + 2 * t;
            float b0 = __ldg(bias + col), b1 = __ldg(bias + col + 1);
            float2 o0 = make_float2(d[mt][nt][0] + b0, d[mt][nt][1] + b1);
            float2 o1 = make_float2(d[mt][nt][2] + b0, d[mt][nt][3] + b1);
            *reinterpret_cast<float2*>(out + (size_t)row * HDIM + col) = o0;
            *reinterpret_cast<float2*>(out + (size_t)(row + 8) * HDIM + col) = o1;
        }
    }
}

extern "C" void kernel_launch(void* const* d_in, const int* in_sizes, int n_in,
                              void* d_out, int out_size)
{
    const float* x    = (const float*)d_in[0];
    const float* y    = (const float*)d_in[1];
    const float* fc1w = (const float*)d_in[2];
    const float* fc1b = (const float*)d_in[3];
    float* out = (float*)d_out;

    float* xattn = nullptr;
    cudaGetSymbolAddress((void**)&xattn, g_xattn);

    attn_kernel<<<BT / PAIRS_PER_BLK, 256>>>(x, y, xattn);

    const int smem_bytes = 2 * 128 * SP * 8;   // 86016
    cudaFuncSetAttribute(gemm_kernel,
                         cudaFuncAttributeMaxDynamicSharedMemorySize, smem_bytes);
    gemm_kernel<<<dim3(HDIM / 128, BT / 128), 256, smem_bytes>>>(xattn, fc1w, fc1b, out);
}